// round 7
// baseline (speedup 1.0000x reference)
#include <cuda_runtime.h>

#define BB 16
#define NN 8192
#define SS 1024
#define KK 32
#define NROWS (BB*SS*KK)        // 524288
#define NINV  (1.0f/524288.0f)  // exact power of two
#define R2 0.04f

typedef unsigned long long ull;

// ---------------- f32x2 packed helpers (Blackwell) ----------------
__device__ __forceinline__ ull pack2(float lo, float hi) {
    ull r;
    asm("mov.b64 %0, {%1, %2};" : "=l"(r) : "r"(__float_as_uint(lo)), "r"(__float_as_uint(hi)));
    return r;
}
__device__ __forceinline__ void unpack2(ull v, float& lo, float& hi) {
    unsigned a, b;
    asm("mov.b64 {%0, %1}, %2;" : "=r"(a), "=r"(b) : "l"(v));
    lo = __uint_as_float(a); hi = __uint_as_float(b);
}
__device__ __forceinline__ ull add2(ull a, ull b) {
    ull d; asm("add.rn.f32x2 %0, %1, %2;" : "=l"(d) : "l"(a), "l"(b)); return d;
}
__device__ __forceinline__ ull mul2(ull a, ull b) {
    ull d; asm("mul.rn.f32x2 %0, %1, %2;" : "=l"(d) : "l"(a), "l"(b)); return d;
}
__device__ __forceinline__ ull fma2(ull a, ull b, ull c) {
    ull d; asm("fma.rn.f32x2 %0, %1, %2, %3;" : "=l"(d) : "l"(a), "l"(b), "l"(c)); return d;
}
__device__ __forceinline__ unsigned redux_max_u32(unsigned v) {
    unsigned r;
    asm("redux.sync.max.u32 %0, %1, 0xffffffff;" : "=r"(r) : "r"(v));
    return r;
}

// ---------------- scratch (device globals: no allocation allowed) ----------------
__device__ int    g_ball[NROWS];
__device__ float4 g_xyzp[BB*NN];
__device__ float4 g_pts4[BB*NN];
__device__ float  g_x[(size_t)NROWS*6];
__device__ float  g_z2[(size_t)NROWS*64];
__device__ float  g_max3[BB*SS*128];
__device__ float  g_min3[BB*SS*128];
__device__ float  g_stats0[27];
__device__ float  g_sum2[64],  g_sumsq2[64];
__device__ float  g_sum3[128], g_sumsq3[128];
__device__ float  g_scale1[64], g_shift1[64];
__device__ float  g_scale2[64], g_shift2[64];
__device__ float  g_scale3[128], g_shift3[128];

// ---------------- zero stats: split into 3 launches so fps is launch #4 (profiled) ----
__global__ void zeroA_kernel() { int t = threadIdx.x; if (t < 27) g_stats0[t] = 0.f; }
__global__ void zeroB_kernel() { int t = threadIdx.x; if (t < 64) { g_sum2[t] = 0.f; g_sumsq2[t] = 0.f; } }
__global__ void zeroC_kernel() { int t = threadIdx.x; if (t < 128) { g_sum3[t] = 0.f; g_sumsq3[t] = 0.f; } }

// ---------------- FPS: one block per batch, 256 thr x 32 pts, 2 syncs/iter ----------
// Also performs "prep" (g_xyzp / g_pts4 packing) for its batch during init.
__global__ __launch_bounds__(256) void fps_kernel(const float* __restrict__ xyz,
                                                  const float* __restrict__ pts,
                                                  float* __restrict__ new_xyz) {
    const int b = blockIdx.x;
    const float* base  = xyz + (size_t)b * NN * 3;
    const float* pbase = pts + (size_t)b * NN * 3;
    const int t = threadIdx.x;

    ull px2[16], py2[16], pz2[16];
    float dist[32];
#pragma unroll
    for (int p = 0; p < 16; p++) {
        int i0 = (2*p)*256 + t, i1 = i0 + 256;
        float x0 = base[3*i0], y0 = base[3*i0+1], z0 = base[3*i0+2];
        float x1 = base[3*i1], y1 = base[3*i1+1], z1 = base[3*i1+2];
        px2[p] = pack2(x0, x1); py2[p] = pack2(y0, y1); pz2[p] = pack2(z0, z1);
        g_xyzp[b*NN + i0] = make_float4(x0, y0, z0, fmaf(x0,x0,fmaf(y0,y0,z0*z0)));
        g_xyzp[b*NN + i1] = make_float4(x1, y1, z1, fmaf(x1,x1,fmaf(y1,y1,z1*z1)));
        g_pts4[b*NN + i0] = make_float4(pbase[3*i0], pbase[3*i0+1], pbase[3*i0+2], 0.f);
        g_pts4[b*NN + i1] = make_float4(pbase[3*i1], pbase[3*i1+1], pbase[3*i1+2], 0.f);
        dist[2*p] = 1e10f; dist[2*p+1] = 1e10f;
    }

    __shared__ unsigned s_M[2];
    __shared__ int      s_idx[2];
    if (t == 0) { s_M[0]=0u; s_M[1]=0u; s_idx[0]=0x7fffffff; s_idx[1]=0x7fffffff; }
    float cx = base[0], cy = base[1], cz = base[2];
    __syncthreads();

    float* out = new_xyz + (size_t)b * SS * 3;
    const int lane = t & 31;
    for (int it = 0; it < SS; it++) {
        if (t == 0) { out[3*it] = cx; out[3*it+1] = cy; out[3*it+2] = cz; }
        const int cur = it & 1, nxt = cur ^ 1;
        ull nx2 = pack2(-cx,-cx), ny2 = pack2(-cy,-cy), nz2 = pack2(-cz,-cz);

        // d = (x-cx)^2+(y-cy)^2+(z-cz)^2 (bit-identical to reference form),
        // dist = min(dist,d), track max value only (4-way tree to shorten dep chain)
        float bv0 = 0.f, bv1 = 0.f, bv2 = 0.f, bv3 = 0.f;
#pragma unroll
        for (int p = 0; p < 16; p++) {
            ull dx = add2(px2[p], nx2);
            ull dy = add2(py2[p], ny2);
            ull dz = add2(pz2[p], nz2);
            ull d2 = fma2(dx, dx, fma2(dy, dy, mul2(dz, dz)));
            float d0, d1; unpack2(d2, d0, d1);
            float n0 = fminf(dist[2*p], d0);   dist[2*p]   = n0;
            float n1 = fminf(dist[2*p+1], d1); dist[2*p+1] = n1;
            if (p & 1) { bv1 = fmaxf(bv1, n0); bv3 = fmaxf(bv3, n1); }
            else       { bv0 = fmaxf(bv0, n0); bv2 = fmaxf(bv2, n1); }
        }
        float bv = fmaxf(fmaxf(bv0, bv1), fmaxf(bv2, bv3));
        // all dists >= 0 -> float bits are monotone under u32 compare
        unsigned mb   = __float_as_uint(bv);
        unsigned wmax = redux_max_u32(mb);
        if (lane == 0) atomicMax(&s_M[cur], wmax);
        __syncthreads();

        unsigned M = s_M[cur];
        if (mb == M) {   // only the winning warp(s) pay for the index search
            int cand = 0x7fffffff;
#pragma unroll
            for (int j = 31; j >= 0; j--)
                if (__float_as_uint(dist[j]) == M) cand = j*256 + t;  // lowest j wins
            atomicMin(&s_idx[cur], cand);    // lowest global index wins (first-occurrence)
        }
        if (t == 0) { s_M[nxt] = 0u; s_idx[nxt] = 0x7fffffff; }  // reset other buffer
        __syncthreads();

        int i2 = s_idx[cur];
        cx = base[3*i2]; cy = base[3*i2+1]; cz = base[3*i2+2];   // broadcast LDG
    }
}

// ---------------- ball query: one warp per centroid, pipelined (MLP=4) ----------------
__global__ __launch_bounds__(256) void ball_kernel(const float* __restrict__ new_xyz) {
    int w    = (blockIdx.x * 256 + threadIdx.x) >> 5;  // global centroid id (b*S+s)
    int lane = threadIdx.x & 31;
    int b    = w >> 10;
    const float4* xp = g_xyzp + b * NN;
    float cx = new_xyz[3*w], cy = new_xyz[3*w+1], cz = new_xyz[3*w+2];
    float ss = fmaf(cx,cx, fmaf(cy,cy, cz*cz));
    int* outp = g_ball + w * KK;

    int count = 0, first = 0;
    for (int base = 0; base < NN && count < KK; base += 128) {
        float4 p0 = xp[base      + lane];
        float4 p1 = xp[base + 32 + lane];
        float4 p2 = xp[base + 64 + lane];
        float4 p3 = xp[base + 96 + lane];
#define BQ_STEP(P, OFF) { \
        float dot = fmaf(cx,(P).x, fmaf(cy,(P).y, cz*(P).z)); \
        float sq  = fmaf(-2.f, dot, ss) + (P).w; \
        bool hit  = !(sq > R2); \
        unsigned m = __ballot_sync(0xffffffffu, hit); \
        if (count == 0 && m) first = base + (OFF) + __ffs(m) - 1; \
        int pos = count + __popc(m & ((1u << lane) - 1u)); \
        if (hit && pos < KK) outp[pos] = base + (OFF) + lane; \
        count += __popc(m); }
        BQ_STEP(p0, 0) BQ_STEP(p1, 32) BQ_STEP(p2, 64) BQ_STEP(p3, 96)
#undef BQ_STEP
    }
    if (count < KK && lane >= count && lane < KK) outp[lane] = first;
}

// ---------------- pass A: gather (batched for MLP), store x, accumulate stats ------
__global__ __launch_bounds__(256) void passA_kernel(const float* __restrict__ new_xyz) {
    int gt = blockIdx.x * 256 + threadIdx.x;   // 65536 threads, 8 rows each
    float acc[27];
#pragma unroll
    for (int q = 0; q < 27; q++) acc[q] = 0.f;

    for (int h = 0; h < 2; h++) {
        int idxs[4];
#pragma unroll
        for (int i = 0; i < 4; i++)
            idxs[i] = g_ball[(h*4 + i) * 65536 + gt];   // 4 independent LDGs

        float4 P[4], Q[4];
        float cen[4][3];
#pragma unroll
        for (int i = 0; i < 4; i++) {                    // 20 independent LDGs in flight
            int row = (h*4 + i) * 65536 + gt;
            int b   = row >> 15;
            int bs  = row >> 5;
            P[i] = g_xyzp[b*NN + idxs[i]];
            Q[i] = g_pts4[b*NN + idxs[i]];
            cen[i][0] = new_xyz[3*bs]; cen[i][1] = new_xyz[3*bs+1]; cen[i][2] = new_xyz[3*bs+2];
        }
#pragma unroll
        for (int i = 0; i < 4; i++) {
            int row = (h*4 + i) * 65536 + gt;
            float f[6];
            f[0] = P[i].x - cen[i][0];
            f[1] = P[i].y - cen[i][1];
            f[2] = P[i].z - cen[i][2];
            f[3] = Q[i].x; f[4] = Q[i].y; f[5] = Q[i].z;
            float2* xr = (float2*)(g_x + (size_t)row * 6);
            xr[0] = make_float2(f[0], f[1]);
            xr[1] = make_float2(f[2], f[3]);
            xr[2] = make_float2(f[4], f[5]);
#pragma unroll
            for (int c = 0; c < 6; c++) acc[c] += f[c];
            int pidx = 6;
#pragma unroll
            for (int a = 0; a < 6; a++)
#pragma unroll
                for (int c = a; c < 6; c++) acc[pidx++] = fmaf(f[a], f[c], acc[pidx]);
        }
    }
#pragma unroll
    for (int q = 0; q < 27; q++) {
        float v = acc[q];
#pragma unroll
        for (int o = 16; o > 0; o >>= 1) v += __shfl_down_sync(0xffffffffu, v, o);
        if ((threadIdx.x & 31) == 0) atomicAdd(&g_stats0[q], v);
    }
}

// ---------------- params1: layer-1 BN stats from Gram ----------------
__global__ void params1_kernel(const float* __restrict__ w1, const float* __restrict__ b1,
                               const float* __restrict__ g1, const float* __restrict__ be1) {
    __shared__ float mu[6], C2[6][6];
    int t = threadIdx.x;
    if (t < 6) mu[t] = g_stats0[t] * NINV;
    if (t < 36) {
        int i = t / 6, j = t % 6;
        int a = i < j ? i : j, c = i < j ? j : i;
        int pos = 6 + 6*a - (a*(a-1))/2 + (c - a);
        C2[i][j] = g_stats0[pos] * NINV;
    }
    __syncthreads();
    if (t < 64) {
        float lin = 0.f;
#pragma unroll
        for (int c = 0; c < 6; c++) lin += w1[t*6+c] * mu[c];
        float m = lin + b1[t];
        float qv = 0.f;
#pragma unroll
        for (int i = 0; i < 6; i++)
#pragma unroll
            for (int j = 0; j < 6; j++) qv += w1[t*6+i] * w1[t*6+j] * C2[i][j];
        float Ez2 = qv + 2.f * b1[t] * lin + b1[t]*b1[t];
        float var = Ez2 - m*m;
        float sc  = g1[t] * rsqrtf(var + 1e-5f);
        g_scale1[t] = sc;
        g_shift1[t] = be1[t] - m * sc;
    }
}

// ---------------- pass B: layer1 (affine-folded) + layer2 GEMM (f32x2, dup weights) ----
// dynamic smem layout (bytes):
//   a1T  float[64][72]  @ 0       (18432)
//   w2d  ull  [64][64]  @ 18432   (32768)   w2d[k][o] = (w,w)
//   w1s  float[384]     @ 51200   (1536)
//   b1s/sc1/sh1/b2s 4x64@ 52736   (1024)
//   psum float[8][64]   @ 53760   (2048)
//   psq  float[8][64]   @ 55808   (2048)   total 57856
#define PB_SMEM 57856
__global__ __launch_bounds__(128) void passB_kernel(const float* __restrict__ w1, const float* __restrict__ b1,
                                                    const float* __restrict__ w2, const float* __restrict__ b2) {
    extern __shared__ char smem[];
    float* a1T = (float*)smem;
    ull*   w2d = (ull*)(smem + 18432);
    float* w1s = (float*)(smem + 51200);
    float* b1s = (float*)(smem + 52736);
    float* sc1 = b1s + 64; float* sh1 = sc1 + 64; float* b2s = sh1 + 64;
    float* psum = (float*)(smem + 53760);
    float* psq  = (float*)(smem + 55808);
    int tid = threadIdx.x;

    for (int i = tid; i < 4096; i += 128) {
        int o = i >> 6, c = i & 63;
        float w = w2[i];
        w2d[c*64 + o] = pack2(w, w);
    }
    for (int i = tid; i < 384; i += 128) w1s[i] = w1[i];
    if (tid < 64) { b1s[tid] = b1[tid]; sc1[tid] = g_scale1[tid]; sh1[tid] = g_shift1[tid]; b2s[tid] = b2[tid]; }
    __syncthreads();

    int rowBase = blockIdx.x * 64;
    {   // stage 1: a1T[o][r] = relu(affine1(W1 x + b1)), transposed store
        int r = tid >> 1, o0 = (tid & 1) * 32;
        const float2* xr = (const float2*)(g_x + (size_t)(rowBase + r) * 6);
        float2 v0 = xr[0], v1 = xr[1], v2 = xr[2];
        float x0=v0.x, x1=v0.y, x2=v1.x, x3=v1.y, x4=v2.x, x5=v2.y;
#pragma unroll
        for (int c = 0; c < 32; c++) {
            int o = o0 + c;
            float z = b1s[o];
            z = fmaf(w1s[o*6+0],x0, z); z = fmaf(w1s[o*6+1],x1, z); z = fmaf(w1s[o*6+2],x2, z);
            z = fmaf(w1s[o*6+3],x3, z); z = fmaf(w1s[o*6+4],x4, z); z = fmaf(w1s[o*6+5],x5, z);
            a1T[o*72 + r] = fmaxf(fmaf(z, sc1[o], sh1[o]), 0.f);
        }
    }
    __syncthreads();

    int tx = tid & 15, ty = tid >> 4;       // tx: 4-col group, ty: 8-row group
    ull acc[4][4];                          // [row-pair][col]
#pragma unroll
    for (int j = 0; j < 4; j++) {
        ull bp = pack2(b2s[tx*4+j], b2s[tx*4+j]);
#pragma unroll
        for (int pi = 0; pi < 4; pi++) acc[pi][j] = bp;
    }

#pragma unroll 8
    for (int k = 0; k < 64; k++) {
        ulonglong2 ap0 = *(const ulonglong2*)&a1T[k*72 + ty*8];
        ulonglong2 ap1 = *(const ulonglong2*)&a1T[k*72 + ty*8 + 4];
        ulonglong2 wp0 = *(const ulonglong2*)&w2d[k*64 + tx*4];
        ulonglong2 wp1 = *(const ulonglong2*)&w2d[k*64 + tx*4 + 2];
        ull ar[4] = {ap0.x, ap0.y, ap1.x, ap1.y};
#pragma unroll
        for (int pi = 0; pi < 4; pi++) {
            acc[pi][0] = fma2(ar[pi], wp0.x, acc[pi][0]);
            acc[pi][1] = fma2(ar[pi], wp0.y, acc[pi][1]);
            acc[pi][2] = fma2(ar[pi], wp1.x, acc[pi][2]);
            acc[pi][3] = fma2(ar[pi], wp1.y, acc[pi][3]);
        }
    }

    float z[8][4];
#pragma unroll
    for (int pi = 0; pi < 4; pi++)
#pragma unroll
        for (int j = 0; j < 4; j++) unpack2(acc[pi][j], z[2*pi][j], z[2*pi+1][j]);

    float cs[4] = {0,0,0,0}, cq[4] = {0,0,0,0};
#pragma unroll
    for (int rr = 0; rr < 8; rr++) {
        float4 v = make_float4(z[rr][0], z[rr][1], z[rr][2], z[rr][3]);
        *(float4*)&g_z2[(size_t)(rowBase + ty*8 + rr) * 64 + tx*4] = v;
        cs[0]+=v.x; cs[1]+=v.y; cs[2]+=v.z; cs[3]+=v.w;
        cq[0]=fmaf(v.x,v.x,cq[0]); cq[1]=fmaf(v.y,v.y,cq[1]);
        cq[2]=fmaf(v.z,v.z,cq[2]); cq[3]=fmaf(v.w,v.w,cq[3]);
    }
#pragma unroll
    for (int j = 0; j < 4; j++) { psum[ty*64 + tx*4+j] = cs[j]; psq[ty*64 + tx*4+j] = cq[j]; }
    __syncthreads();
    if (tid < 64) {
        float s = 0.f, s2 = 0.f;
#pragma unroll
        for (int y = 0; y < 8; y++) { s += psum[y*64 + tid]; s2 += psq[y*64 + tid]; }
        atomicAdd(&g_sum2[tid], s);
        atomicAdd(&g_sumsq2[tid], s2);
    }
}

__global__ void params2_kernel(const float* __restrict__ g2, const float* __restrict__ be2) {
    int t = threadIdx.x;
    if (t < 64) {
        float m = g_sum2[t] * NINV;
        float var = g_sumsq2[t] * NINV - m*m;
        float sc = g2[t] * rsqrtf(var + 1e-5f);
        g_scale2[t] = sc; g_shift2[t] = be2[t] - m * sc;
    }
}

// ---------------- pass C: layer3 GEMM (f32x2, dup weights) + stats + group max/min ----
// dynamic smem layout (bytes):
//   a2T  float[64][72]  @ 0       (18432)
//   w3d  ull  [64][64]  @ 18432   (32768)
//   sc2/sh2/b3s 3x64    @ 51200   (768)
//   psum @ 51968, psq @ 54016, pmax @ 56064, pmin @ 58112 (each 2048)  total 60160
#define PC_SMEM 60160
__global__ __launch_bounds__(128) void passC_kernel(const float* __restrict__ w3, const float* __restrict__ b3) {
    extern __shared__ char smem[];
    float* a2T = (float*)smem;
    ull*   w3d = (ull*)(smem + 18432);
    float* sc2 = (float*)(smem + 51200);
    float* sh2 = sc2 + 64; float* b3s = sh2 + 64;
    float* psum = (float*)(smem + 51968);
    float* psq  = (float*)(smem + 54016);
    float* pmax = (float*)(smem + 56064);
    float* pmin = (float*)(smem + 58112);
    int tid = threadIdx.x;
    int colBase = blockIdx.y * 64;

    for (int i = tid; i < 4096; i += 128) {
        int o = i >> 6, c = i & 63;
        float w = w3[(size_t)colBase * 64 + i];   // = w3[(colBase+o)*64 + c], contiguous read
        w3d[c*64 + o] = pack2(w, w);
    }
    if (tid < 64) { sc2[tid] = g_scale2[tid]; sh2[tid] = g_shift2[tid]; b3s[tid] = b3[colBase + tid]; }
    __syncthreads();

    int rowBase = blockIdx.x * 64;
    {   // stage 1: a2T[o][r] = relu(affine2(z2)), transposed store
        int r = tid >> 1, o0 = (tid & 1) * 32;
        const float* zr = g_z2 + (size_t)(rowBase + r) * 64 + o0;
#pragma unroll
        for (int q = 0; q < 8; q++) {
            float4 v = *(const float4*)&zr[q*4];
            int o = o0 + q*4;
            a2T[(o  )*72 + r] = fmaxf(fmaf(v.x, sc2[o  ], sh2[o  ]), 0.f);
            a2T[(o+1)*72 + r] = fmaxf(fmaf(v.y, sc2[o+1], sh2[o+1]), 0.f);
            a2T[(o+2)*72 + r] = fmaxf(fmaf(v.z, sc2[o+2], sh2[o+2]), 0.f);
            a2T[(o+3)*72 + r] = fmaxf(fmaf(v.w, sc2[o+3], sh2[o+3]), 0.f);
        }
    }
    __syncthreads();

    int tx = tid & 15, ty = tid >> 4;
    ull acc[4][4];
#pragma unroll
    for (int j = 0; j < 4; j++) {
        ull bp = pack2(b3s[tx*4+j], b3s[tx*4+j]);
#pragma unroll
        for (int pi = 0; pi < 4; pi++) acc[pi][j] = bp;
    }

#pragma unroll 8
    for (int k = 0; k < 64; k++) {
        ulonglong2 ap0 = *(const ulonglong2*)&a2T[k*72 + ty*8];
        ulonglong2 ap1 = *(const ulonglong2*)&a2T[k*72 + ty*8 + 4];
        ulonglong2 wp0 = *(const ulonglong2*)&w3d[k*64 + tx*4];
        ulonglong2 wp1 = *(const ulonglong2*)&w3d[k*64 + tx*4 + 2];
        ull ar[4] = {ap0.x, ap0.y, ap1.x, ap1.y};
#pragma unroll
        for (int pi = 0; pi < 4; pi++) {
            acc[pi][0] = fma2(ar[pi], wp0.x, acc[pi][0]);
            acc[pi][1] = fma2(ar[pi], wp0.y, acc[pi][1]);
            acc[pi][2] = fma2(ar[pi], wp1.x, acc[pi][2]);
            acc[pi][3] = fma2(ar[pi], wp1.y, acc[pi][3]);
        }
    }

    float z[8][4];
#pragma unroll
    for (int pi = 0; pi < 4; pi++)
#pragma unroll
        for (int j = 0; j < 4; j++) unpack2(acc[pi][j], z[2*pi][j], z[2*pi+1][j]);

    float cs[4] = {0,0,0,0}, cq[4] = {0,0,0,0};
    float mx[4] = {-1e30f,-1e30f,-1e30f,-1e30f}, mn[4] = {1e30f,1e30f,1e30f,1e30f};
#pragma unroll
    for (int rr = 0; rr < 8; rr++) {
#pragma unroll
        for (int j = 0; j < 4; j++) {
            float v = z[rr][j];
            cs[j] += v; cq[j] = fmaf(v, v, cq[j]);
            mx[j] = fmaxf(mx[j], v); mn[j] = fminf(mn[j], v);
        }
    }
#pragma unroll
    for (int j = 0; j < 4; j++) {
        psum[ty*64 + tx*4+j] = cs[j]; psq[ty*64 + tx*4+j] = cq[j];
        pmax[ty*64 + tx*4+j] = mx[j]; pmin[ty*64 + tx*4+j] = mn[j];
    }
    __syncthreads();
    if (tid < 64) {
        float s = 0.f, s2 = 0.f;
#pragma unroll
        for (int y = 0; y < 8; y++) { s += psum[y*64 + tid]; s2 += psq[y*64 + tid]; }
        atomicAdd(&g_sum3[colBase + tid], s);
        atomicAdd(&g_sumsq3[colBase + tid], s2);
    }
    {   // per-32-row-group max/min: group 0 = ty 0..3, group 1 = ty 4..7
        int g = tid >> 6, c = tid & 63;
        float M = -1e30f, m = 1e30f;
#pragma unroll
        for (int y = 0; y < 4; y++) {
            M = fmaxf(M, pmax[(g*4 + y)*64 + c]);
            m = fminf(m, pmin[(g*4 + y)*64 + c]);
        }
        int gid = blockIdx.x * 2 + g;
        g_max3[(size_t)gid * 128 + colBase + c] = M;
        g_min3[(size_t)gid * 128 + colBase + c] = m;
    }
}

__global__ void params3_kernel(const float* __restrict__ g3, const float* __restrict__ be3) {
    int t = threadIdx.x;
    if (t < 128) {
        float m = g_sum3[t] * NINV;
        float var = g_sumsq3[t] * NINV - m*m;
        float sc = g3[t] * rsqrtf(var + 1e-5f);
        g_scale3[t] = sc; g_shift3[t] = be3[t] - m * sc;
    }
}

// ---------------- pass D: affine3 on pre-reduced max/min + relu ----------------
__global__ __launch_bounds__(256) void passD_kernel(float* __restrict__ out_pts) {
    int idx = blockIdx.x * 256 + threadIdx.x;   // gid*128 + c, 2M total
    int c = idx & 127;
    float sc = g_scale3[c], sh = g_shift3[c];
    float v = (sc >= 0.f) ? g_max3[idx] : g_min3[idx];
    out_pts[idx] = fmaxf(fmaf(v, sc, sh), 0.f);
}

// ---------------- launch ----------------
extern "C" void kernel_launch(void* const* d_in, const int* in_sizes, int n_in,
                              void* d_out, int out_size) {
    const float* xyz = (const float*)d_in[0];
    const float* pts = (const float*)d_in[1];
    const float* w1  = (const float*)d_in[2];
    const float* b1  = (const float*)d_in[3];
    const float* g1  = (const float*)d_in[4];
    const float* be1 = (const float*)d_in[5];
    const float* w2  = (const float*)d_in[6];
    const float* b2  = (const float*)d_in[7];
    const float* g2  = (const float*)d_in[8];
    const float* be2 = (const float*)d_in[9];
    const float* w3  = (const float*)d_in[10];
    const float* b3  = (const float*)d_in[11];
    const float* g3  = (const float*)d_in[12];
    const float* be3 = (const float*)d_in[13];

    float* out      = (float*)d_out;
    float* new_xyz  = out;                 // 16*1024*3 = 49152 floats
    float* new_pts  = out + 49152;         // 16*1024*128 floats

    static int attr_done = 0;
    if (!attr_done) {
        cudaFuncSetAttribute(passB_kernel, cudaFuncAttributeMaxDynamicSharedMemorySize, PB_SMEM);
        cudaFuncSetAttribute(passC_kernel, cudaFuncAttributeMaxDynamicSharedMemorySize, PC_SMEM);
        attr_done = 1;
    }

    zeroA_kernel<<<1, 32>>>();
    zeroB_kernel<<<1, 64>>>();
    zeroC_kernel<<<1, 128>>>();
    fps_kernel<<<BB, 256>>>(xyz, pts, new_xyz);      // launch #4 -> profiled
    ball_kernel<<<2048, 256>>>(new_xyz);
    passA_kernel<<<256, 256>>>(new_xyz);
    params1_kernel<<<1, 64>>>(w1, b1, g1, be1);
    passB_kernel<<<8192, 128, PB_SMEM>>>(w1, b1, w2, b2);
    params2_kernel<<<1, 64>>>(g2, be2);
    passC_kernel<<<dim3(8192, 2), 128, PC_SMEM>>>(w3, b3);
    params3_kernel<<<1, 128>>>(g3, be3);
    passD_kernel<<<8192, 256>>>(new_pts);
}

// round 12
// speedup vs baseline: 1.1343x; 1.1343x over previous
#include <cuda_runtime.h>

#define BB 16
#define NN 8192
#define SS 1024
#define KK 32
#define NROWS (BB*SS*KK)        // 524288
#define NINV  (1.0f/524288.0f)  // exact power of two
#define R2 0.04f

typedef unsigned long long ull;

// ---------------- f32x2 packed helpers (Blackwell) ----------------
__device__ __forceinline__ ull pack2(float lo, float hi) {
    ull r;
    asm("mov.b64 %0, {%1, %2};" : "=l"(r) : "r"(__float_as_uint(lo)), "r"(__float_as_uint(hi)));
    return r;
}
__device__ __forceinline__ void unpack2(ull v, float& lo, float& hi) {
    unsigned a, b;
    asm("mov.b64 {%0, %1}, %2;" : "=r"(a), "=r"(b) : "l"(v));
    lo = __uint_as_float(a); hi = __uint_as_float(b);
}
__device__ __forceinline__ ull add2(ull a, ull b) {
    ull d; asm("add.rn.f32x2 %0, %1, %2;" : "=l"(d) : "l"(a), "l"(b)); return d;
}
__device__ __forceinline__ ull mul2(ull a, ull b) {
    ull d; asm("mul.rn.f32x2 %0, %1, %2;" : "=l"(d) : "l"(a), "l"(b)); return d;
}
__device__ __forceinline__ ull fma2(ull a, ull b, ull c) {
    ull d; asm("fma.rn.f32x2 %0, %1, %2, %3;" : "=l"(d) : "l"(a), "l"(b), "l"(c)); return d;
}
__device__ __forceinline__ unsigned redux_max_u32(unsigned v) {
    unsigned r;
    asm("redux.sync.max.u32 %0, %1, 0xffffffff;" : "=r"(r) : "r"(v));
    return r;
}

// ---------------- scratch (device globals: no allocation allowed) ----------------
__device__ int    g_ball[NROWS];
__device__ float4 g_xyzp[BB*NN];
__device__ float4 g_pts4[BB*NN];
__device__ float  g_x[(size_t)NROWS*6];
__device__ float  g_z2[(size_t)NROWS*64];
__device__ float  g_max3[BB*SS*128];
__device__ float  g_min3[BB*SS*128];
__device__ float  g_stats0[27];
__device__ float  g_sum2[64],  g_sumsq2[64];
__device__ float  g_sum3[128], g_sumsq3[128];
__device__ float  g_scale1[64], g_shift1[64];
__device__ float  g_scale2[64], g_shift2[64];
__device__ float  g_scale3[128], g_shift3[128];

// ---------------- zero stats: split into 3 launches so fps is launch #4 (profiled) ----
__global__ void zeroA_kernel() { int t = threadIdx.x; if (t < 27) g_stats0[t] = 0.f; }
__global__ void zeroB_kernel() { int t = threadIdx.x; if (t < 64) { g_sum2[t] = 0.f; g_sumsq2[t] = 0.f; } }
__global__ void zeroC_kernel() { int t = threadIdx.x; if (t < 128) { g_sum3[t] = 0.f; g_sumsq3[t] = 0.f; } }

// ---------------- FPS: one block per batch, 512 thr x 16 pts, 2 syncs/iter ----------
// Also performs "prep" (g_xyzp / g_pts4 packing) for its batch during init.
__global__ __launch_bounds__(512) void fps_kernel(const float* __restrict__ xyz,
                                                  const float* __restrict__ pts,
                                                  float* __restrict__ new_xyz) {
    const int b = blockIdx.x;
    const float* base  = xyz + (size_t)b * NN * 3;
    const float* pbase = pts + (size_t)b * NN * 3;
    const int t = threadIdx.x;

    ull px2[8], py2[8], pz2[8];
    float dist[16];
#pragma unroll
    for (int p = 0; p < 8; p++) {
        int i0 = (2*p)*512 + t, i1 = i0 + 512;
        float x0 = base[3*i0], y0 = base[3*i0+1], z0 = base[3*i0+2];
        float x1 = base[3*i1], y1 = base[3*i1+1], z1 = base[3*i1+2];
        px2[p] = pack2(x0, x1); py2[p] = pack2(y0, y1); pz2[p] = pack2(z0, z1);
        g_xyzp[b*NN + i0] = make_float4(x0, y0, z0, fmaf(x0,x0,fmaf(y0,y0,z0*z0)));
        g_xyzp[b*NN + i1] = make_float4(x1, y1, z1, fmaf(x1,x1,fmaf(y1,y1,z1*z1)));
        g_pts4[b*NN + i0] = make_float4(pbase[3*i0], pbase[3*i0+1], pbase[3*i0+2], 0.f);
        g_pts4[b*NN + i1] = make_float4(pbase[3*i1], pbase[3*i1+1], pbase[3*i1+2], 0.f);
        dist[2*p] = 1e10f; dist[2*p+1] = 1e10f;
    }

    __shared__ unsigned s_M[2];
    __shared__ int      s_idx[2];
    if (t == 0) { s_M[0]=0u; s_M[1]=0u; s_idx[0]=0x7fffffff; s_idx[1]=0x7fffffff; }
    float cx = base[0], cy = base[1], cz = base[2];
    __syncthreads();

    float* out = new_xyz + (size_t)b * SS * 3;
    const int lane = t & 31;
    for (int it = 0; it < SS; it++) {
        if (t == 0) { out[3*it] = cx; out[3*it+1] = cy; out[3*it+2] = cz; }
        const int cur = it & 1, nxt = cur ^ 1;
        ull nx2 = pack2(-cx,-cx), ny2 = pack2(-cy,-cy), nz2 = pack2(-cz,-cz);

        // d = (x-cx)^2+(y-cy)^2+(z-cz)^2 (bit-identical to reference form),
        // dist = min(dist,d), track max value only (4-way tree to shorten dep chain)
        float bv0 = 0.f, bv1 = 0.f, bv2 = 0.f, bv3 = 0.f;
#pragma unroll
        for (int p = 0; p < 8; p++) {
            ull dx = add2(px2[p], nx2);
            ull dy = add2(py2[p], ny2);
            ull dz = add2(pz2[p], nz2);
            ull d2 = fma2(dx, dx, fma2(dy, dy, mul2(dz, dz)));
            float d0, d1; unpack2(d2, d0, d1);
            float n0 = fminf(dist[2*p], d0);   dist[2*p]   = n0;
            float n1 = fminf(dist[2*p+1], d1); dist[2*p+1] = n1;
            if (p & 1) { bv1 = fmaxf(bv1, n0); bv3 = fmaxf(bv3, n1); }
            else       { bv0 = fmaxf(bv0, n0); bv2 = fmaxf(bv2, n1); }
        }
        float bv = fmaxf(fmaxf(bv0, bv1), fmaxf(bv2, bv3));
        // all dists >= 0 -> float bits are monotone under u32 compare
        unsigned mb   = __float_as_uint(bv);
        unsigned wmax = redux_max_u32(mb);
        if (lane == 0) atomicMax(&s_M[cur], wmax);
        __syncthreads();

        unsigned M = s_M[cur];
        if (mb == M) {   // only the winning warp(s) pay for the index search
            int cand = 0x7fffffff;
#pragma unroll
            for (int j = 15; j >= 0; j--)
                if (__float_as_uint(dist[j]) == M) cand = j*512 + t;  // lowest j wins
            atomicMin(&s_idx[cur], cand);    // lowest global index wins (first-occurrence)
        }
        if (t == 0) { s_M[nxt] = 0u; s_idx[nxt] = 0x7fffffff; }  // reset other buffer
        __syncthreads();

        int i2 = s_idx[cur];
        cx = base[3*i2]; cy = base[3*i2+1]; cz = base[3*i2+2];   // broadcast LDG
    }
}

// ---------------- ball query: one warp per centroid, pipelined (MLP=4) ----------------
__global__ __launch_bounds__(256) void ball_kernel(const float* __restrict__ new_xyz) {
    int w    = (blockIdx.x * 256 + threadIdx.x) >> 5;  // global centroid id (b*S+s)
    int lane = threadIdx.x & 31;
    int b    = w >> 10;
    const float4* xp = g_xyzp + b * NN;
    float cx = new_xyz[3*w], cy = new_xyz[3*w+1], cz = new_xyz[3*w+2];
    float ss = fmaf(cx,cx, fmaf(cy,cy, cz*cz));
    int* outp = g_ball + w * KK;

    int count = 0, first = 0;
    for (int base = 0; base < NN && count < KK; base += 128) {
        float4 p0 = xp[base      + lane];
        float4 p1 = xp[base + 32 + lane];
        float4 p2 = xp[base + 64 + lane];
        float4 p3 = xp[base + 96 + lane];
#define BQ_STEP(P, OFF) { \
        float dot = fmaf(cx,(P).x, fmaf(cy,(P).y, cz*(P).z)); \
        float sq  = fmaf(-2.f, dot, ss) + (P).w; \
        bool hit  = !(sq > R2); \
        unsigned m = __ballot_sync(0xffffffffu, hit); \
        if (count == 0 && m) first = base + (OFF) + __ffs(m) - 1; \
        int pos = count + __popc(m & ((1u << lane) - 1u)); \
        if (hit && pos < KK) outp[pos] = base + (OFF) + lane; \
        count += __popc(m); }
        BQ_STEP(p0, 0) BQ_STEP(p1, 32) BQ_STEP(p2, 64) BQ_STEP(p3, 96)
#undef BQ_STEP
    }
    if (count < KK && lane >= count && lane < KK) outp[lane] = first;
}

// ---------------- pass A: gather (batched for MLP), store x, accumulate stats ------
__global__ __launch_bounds__(256) void passA_kernel(const float* __restrict__ new_xyz) {
    int gt = blockIdx.x * 256 + threadIdx.x;   // 65536 threads, 8 rows each
    float acc[27];
#pragma unroll
    for (int q = 0; q < 27; q++) acc[q] = 0.f;

    for (int h = 0; h < 2; h++) {
        int idxs[4];
#pragma unroll
        for (int i = 0; i < 4; i++)
            idxs[i] = g_ball[(h*4 + i) * 65536 + gt];   // 4 independent LDGs

        float4 P[4], Q[4];
        float cen[4][3];
#pragma unroll
        for (int i = 0; i < 4; i++) {                    // 20 independent LDGs in flight
            int row = (h*4 + i) * 65536 + gt;
            int b   = row >> 15;
            int bs  = row >> 5;
            P[i] = g_xyzp[b*NN + idxs[i]];
            Q[i] = g_pts4[b*NN + idxs[i]];
            cen[i][0] = new_xyz[3*bs]; cen[i][1] = new_xyz[3*bs+1]; cen[i][2] = new_xyz[3*bs+2];
        }
#pragma unroll
        for (int i = 0; i < 4; i++) {
            int row = (h*4 + i) * 65536 + gt;
            float f[6];
            f[0] = P[i].x - cen[i][0];
            f[1] = P[i].y - cen[i][1];
            f[2] = P[i].z - cen[i][2];
            f[3] = Q[i].x; f[4] = Q[i].y; f[5] = Q[i].z;
            float2* xr = (float2*)(g_x + (size_t)row * 6);
            xr[0] = make_float2(f[0], f[1]);
            xr[1] = make_float2(f[2], f[3]);
            xr[2] = make_float2(f[4], f[5]);
#pragma unroll
            for (int c = 0; c < 6; c++) acc[c] += f[c];
            int pidx = 6;
#pragma unroll
            for (int a = 0; a < 6; a++)
#pragma unroll
                for (int c = a; c < 6; c++) acc[pidx++] = fmaf(f[a], f[c], acc[pidx]);
        }
    }
#pragma unroll
    for (int q = 0; q < 27; q++) {
        float v = acc[q];
#pragma unroll
        for (int o = 16; o > 0; o >>= 1) v += __shfl_down_sync(0xffffffffu, v, o);
        if ((threadIdx.x & 31) == 0) atomicAdd(&g_stats0[q], v);
    }
}

// ---------------- params1: layer-1 BN stats from Gram ----------------
__global__ void params1_kernel(const float* __restrict__ w1, const float* __restrict__ b1,
                               const float* __restrict__ g1, const float* __restrict__ be1) {
    __shared__ float mu[6], C2[6][6];
    int t = threadIdx.x;
    if (t < 6) mu[t] = g_stats0[t] * NINV;
    if (t < 36) {
        int i = t / 6, j = t % 6;
        int a = i < j ? i : j, c = i < j ? j : i;
        int pos = 6 + 6*a - (a*(a-1))/2 + (c - a);
        C2[i][j] = g_stats0[pos] * NINV;
    }
    __syncthreads();
    if (t < 64) {
        float lin = 0.f;
#pragma unroll
        for (int c = 0; c < 6; c++) lin += w1[t*6+c] * mu[c];
        float m = lin + b1[t];
        float qv = 0.f;
#pragma unroll
        for (int i = 0; i < 6; i++)
#pragma unroll
            for (int j = 0; j < 6; j++) qv += w1[t*6+i] * w1[t*6+j] * C2[i][j];
        float Ez2 = qv + 2.f * b1[t] * lin + b1[t]*b1[t];
        float var = Ez2 - m*m;
        float sc  = g1[t] * rsqrtf(var + 1e-5f);
        g_scale1[t] = sc;
        g_shift1[t] = be1[t] - m * sc;
    }
}

// ---------------- pass B: layer1 (affine-folded) + layer2 GEMM (f32x2) + z2 stats ----------------
__global__ __launch_bounds__(128) void passB_kernel(const float* __restrict__ w1, const float* __restrict__ b1,
                                                    const float* __restrict__ w2, const float* __restrict__ b2) {
    __shared__ __align__(16) float a1T[64][72];   // [k][row]
    __shared__ __align__(16) float w2s[64][64];   // [k][o]
    __shared__ float w1s[64][6], b1s[64], sc1[64], sh1[64], b2s[64];
    __shared__ float psum[8][64], psq[8][64];
    int tid = threadIdx.x;

    for (int i = tid; i < 4096; i += 128) { int o = i >> 6, c = i & 63; w2s[c][o] = w2[i]; }
    for (int i = tid; i < 384; i += 128) w1s[i/6][i%6] = w1[i];
    if (tid < 64) { b1s[tid] = b1[tid]; sc1[tid] = g_scale1[tid]; sh1[tid] = g_shift1[tid]; b2s[tid] = b2[tid]; }
    __syncthreads();

    int rowBase = blockIdx.x * 64;
    {   // stage 1: a1T[o][r] = relu(affine1(W1 x + b1)), transposed store
        int r = tid >> 1, o0 = (tid & 1) * 32;
        const float2* xr2 = (const float2*)(g_x + (size_t)(rowBase + r) * 6);
        float2 v0 = xr2[0], v1 = xr2[1], v2 = xr2[2];
        float x0=v0.x, x1=v0.y, x2=v1.x, x3=v1.y, x4=v2.x, x5=v2.y;
#pragma unroll
        for (int c = 0; c < 32; c++) {
            int o = o0 + c;
            float z = b1s[o];
            z = fmaf(w1s[o][0],x0, z); z = fmaf(w1s[o][1],x1, z); z = fmaf(w1s[o][2],x2, z);
            z = fmaf(w1s[o][3],x3, z); z = fmaf(w1s[o][4],x4, z); z = fmaf(w1s[o][5],x5, z);
            a1T[o][r] = fmaxf(fmaf(z, sc1[o], sh1[o]), 0.f);
        }
    }
    __syncthreads();

    int tx = tid & 15, ty = tid >> 4;       // tx: 4-col group, ty: 8-row group
    ull acc[4][4];                          // [row-pair][col]
#pragma unroll
    for (int j = 0; j < 4; j++) {
        ull bp = pack2(b2s[tx*4+j], b2s[tx*4+j]);
#pragma unroll
        for (int pi = 0; pi < 4; pi++) acc[pi][j] = bp;
    }

#pragma unroll 8
    for (int k = 0; k < 64; k++) {
        ulonglong2 ap0 = *(const ulonglong2*)&a1T[k][ty*8];
        ulonglong2 ap1 = *(const ulonglong2*)&a1T[k][ty*8 + 4];
        float4 wv = *(const float4*)&w2s[k][tx*4];
        ull wd0 = pack2(wv.x, wv.x), wd1 = pack2(wv.y, wv.y);
        ull wd2 = pack2(wv.z, wv.z), wd3 = pack2(wv.w, wv.w);
        ull ar[4] = {ap0.x, ap0.y, ap1.x, ap1.y};
#pragma unroll
        for (int pi = 0; pi < 4; pi++) {
            acc[pi][0] = fma2(ar[pi], wd0, acc[pi][0]);
            acc[pi][1] = fma2(ar[pi], wd1, acc[pi][1]);
            acc[pi][2] = fma2(ar[pi], wd2, acc[pi][2]);
            acc[pi][3] = fma2(ar[pi], wd3, acc[pi][3]);
        }
    }

    float z[8][4];
#pragma unroll
    for (int pi = 0; pi < 4; pi++)
#pragma unroll
        for (int j = 0; j < 4; j++) unpack2(acc[pi][j], z[2*pi][j], z[2*pi+1][j]);

    float cs[4] = {0,0,0,0}, cq[4] = {0,0,0,0};
#pragma unroll
    for (int rr = 0; rr < 8; rr++) {
        float4 v = make_float4(z[rr][0], z[rr][1], z[rr][2], z[rr][3]);
        *(float4*)&g_z2[(size_t)(rowBase + ty*8 + rr) * 64 + tx*4] = v;
        cs[0]+=v.x; cs[1]+=v.y; cs[2]+=v.z; cs[3]+=v.w;
        cq[0]=fmaf(v.x,v.x,cq[0]); cq[1]=fmaf(v.y,v.y,cq[1]);
        cq[2]=fmaf(v.z,v.z,cq[2]); cq[3]=fmaf(v.w,v.w,cq[3]);
    }
#pragma unroll
    for (int j = 0; j < 4; j++) { psum[ty][tx*4+j] = cs[j]; psq[ty][tx*4+j] = cq[j]; }
    __syncthreads();
    if (tid < 64) {
        float s = 0.f, s2 = 0.f;
#pragma unroll
        for (int y = 0; y < 8; y++) { s += psum[y][tid]; s2 += psq[y][tid]; }
        atomicAdd(&g_sum2[tid], s);
        atomicAdd(&g_sumsq2[tid], s2);
    }
}

__global__ void params2_kernel(const float* __restrict__ g2, const float* __restrict__ be2) {
    int t = threadIdx.x;
    if (t < 64) {
        float m = g_sum2[t] * NINV;
        float var = g_sumsq2[t] * NINV - m*m;
        float sc = g2[t] * rsqrtf(var + 1e-5f);
        g_scale2[t] = sc; g_shift2[t] = be2[t] - m * sc;
    }
}

// ---------------- pass C: layer3 GEMM (f32x2) + z3 stats + per-group max/min (no z3 store) ----------------
__global__ __launch_bounds__(128) void passC_kernel(const float* __restrict__ w3, const float* __restrict__ b3) {
    __shared__ __align__(16) float a2T[64][72];   // [k][row]
    __shared__ __align__(16) float w3s[64][64];   // [k][o-in-half]
    __shared__ float sc2[64], sh2[64], b3s[64];
    __shared__ float psum[8][64], psq[8][64], pmax[8][64], pmin[8][64];
    int tid = threadIdx.x;
    int colBase = blockIdx.y * 64;

    for (int i = tid; i < 4096; i += 128) {
        int o = i >> 6, c = i & 63;
        w3s[c][o] = w3[(size_t)colBase * 64 + i];   // = w3[(colBase+o)*64 + c], contiguous read
    }
    if (tid < 64) { sc2[tid] = g_scale2[tid]; sh2[tid] = g_shift2[tid]; b3s[tid] = b3[colBase + tid]; }
    __syncthreads();

    int rowBase = blockIdx.x * 64;
    {   // stage 1: a2T[o][r] = relu(affine2(z2)), transposed store
        int r = tid >> 1, o0 = (tid & 1) * 32;
        const float* zr = g_z2 + (size_t)(rowBase + r) * 64 + o0;
#pragma unroll
        for (int q = 0; q < 8; q++) {
            float4 v = *(const float4*)&zr[q*4];
            int o = o0 + q*4;
            a2T[o  ][r] = fmaxf(fmaf(v.x, sc2[o  ], sh2[o  ]), 0.f);
            a2T[o+1][r] = fmaxf(fmaf(v.y, sc2[o+1], sh2[o+1]), 0.f);
            a2T[o+2][r] = fmaxf(fmaf(v.z, sc2[o+2], sh2[o+2]), 0.f);
            a2T[o+3][r] = fmaxf(fmaf(v.w, sc2[o+3], sh2[o+3]), 0.f);
        }
    }
    __syncthreads();

    int tx = tid & 15, ty = tid >> 4;
    ull acc[4][4];
#pragma unroll
    for (int j = 0; j < 4; j++) {
        ull bp = pack2(b3s[tx*4+j], b3s[tx*4+j]);
#pragma unroll
        for (int pi = 0; pi < 4; pi++) acc[pi][j] = bp;
    }

#pragma unroll 8
    for (int k = 0; k < 64; k++) {
        ulonglong2 ap0 = *(const ulonglong2*)&a2T[k][ty*8];
        ulonglong2 ap1 = *(const ulonglong2*)&a2T[k][ty*8 + 4];
        float4 wv = *(const float4*)&w3s[k][tx*4];
        ull wd0 = pack2(wv.x, wv.x), wd1 = pack2(wv.y, wv.y);
        ull wd2 = pack2(wv.z, wv.z), wd3 = pack2(wv.w, wv.w);
        ull ar[4] = {ap0.x, ap0.y, ap1.x, ap1.y};
#pragma unroll
        for (int pi = 0; pi < 4; pi++) {
            acc[pi][0] = fma2(ar[pi], wd0, acc[pi][0]);
            acc[pi][1] = fma2(ar[pi], wd1, acc[pi][1]);
            acc[pi][2] = fma2(ar[pi], wd2, acc[pi][2]);
            acc[pi][3] = fma2(ar[pi], wd3, acc[pi][3]);
        }
    }

    float z[8][4];
#pragma unroll
    for (int pi = 0; pi < 4; pi++)
#pragma unroll
        for (int j = 0; j < 4; j++) unpack2(acc[pi][j], z[2*pi][j], z[2*pi+1][j]);

    float cs[4] = {0,0,0,0}, cq[4] = {0,0,0,0};
    float mx[4] = {-1e30f,-1e30f,-1e30f,-1e30f}, mn[4] = {1e30f,1e30f,1e30f,1e30f};
#pragma unroll
    for (int rr = 0; rr < 8; rr++) {
#pragma unroll
        for (int j = 0; j < 4; j++) {
            float v = z[rr][j];
            cs[j] += v; cq[j] = fmaf(v, v, cq[j]);
            mx[j] = fmaxf(mx[j], v); mn[j] = fminf(mn[j], v);
        }
    }
#pragma unroll
    for (int j = 0; j < 4; j++) {
        psum[ty][tx*4+j] = cs[j]; psq[ty][tx*4+j] = cq[j];
        pmax[ty][tx*4+j] = mx[j]; pmin[ty][tx*4+j] = mn[j];
    }
    __syncthreads();
    if (tid < 64) {
        float s = 0.f, s2 = 0.f;
#pragma unroll
        for (int y = 0; y < 8; y++) { s += psum[y][tid]; s2 += psq[y][tid]; }
        atomicAdd(&g_sum3[colBase + tid], s);
        atomicAdd(&g_sumsq3[colBase + tid], s2);
    }
    {   // per-32-row-group max/min: group 0 = ty 0..3, group 1 = ty 4..7
        int g = tid >> 6, c = tid & 63;
        float M = -1e30f, m = 1e30f;
#pragma unroll
        for (int y = 0; y < 4; y++) {
            M = fmaxf(M, pmax[g*4 + y][c]);
            m = fminf(m, pmin[g*4 + y][c]);
        }
        int gid = blockIdx.x * 2 + g;
        g_max3[(size_t)gid * 128 + colBase + c] = M;
        g_min3[(size_t)gid * 128 + colBase + c] = m;
    }
}

__global__ void params3_kernel(const float* __restrict__ g3, const float* __restrict__ be3) {
    int t = threadIdx.x;
    if (t < 128) {
        float m = g_sum3[t] * NINV;
        float var = g_sumsq3[t] * NINV - m*m;
        float sc = g3[t] * rsqrtf(var + 1e-5f);
        g_scale3[t] = sc; g_shift3[t] = be3[t] - m * sc;
    }
}

// ---------------- pass D: affine3 on pre-reduced max/min + relu ----------------
__global__ __launch_bounds__(256) void passD_kernel(float* __restrict__ out_pts) {
    int idx = blockIdx.x * 256 + threadIdx.x;   // gid*128 + c, 2M total
    int c = idx & 127;
    float sc = g_scale3[c], sh = g_shift3[c];
    float v = (sc >= 0.f) ? g_max3[idx] : g_min3[idx];
    out_pts[idx] = fmaxf(fmaf(v, sc, sh), 0.f);
}

// ---------------- launch ----------------
extern "C" void kernel_launch(void* const* d_in, const int* in_sizes, int n_in,
                              void* d_out, int out_size) {
    const float* xyz = (const float*)d_in[0];
    const float* pts = (const float*)d_in[1];
    const float* w1  = (const float*)d_in[2];
    const float* b1  = (const float*)d_in[3];
    const float* g1  = (const float*)d_in[4];
    const float* be1 = (const float*)d_in[5];
    const float* w2  = (const float*)d_in[6];
    const float* b2  = (const float*)d_in[7];
    const float* g2  = (const float*)d_in[8];
    const float* be2 = (const float*)d_in[9];
    const float* w3  = (const float*)d_in[10];
    const float* b3  = (const float*)d_in[11];
    const float* g3  = (const float*)d_in[12];
    const float* be3 = (const float*)d_in[13];

    float* out      = (float*)d_out;
    float* new_xyz  = out;                 // 16*1024*3 = 49152 floats
    float* new_pts  = out + 49152;         // 16*1024*128 floats

    zeroA_kernel<<<1, 32>>>();
    zeroB_kernel<<<1, 64>>>();
    zeroC_kernel<<<1, 128>>>();
    fps_kernel<<<BB, 512>>>(xyz, pts, new_xyz);      // launch #4 -> profiled
    ball_kernel<<<2048, 256>>>(new_xyz);
    passA_kernel<<<256, 256>>>(new_xyz);
    params1_kernel<<<1, 64>>>(w1, b1, g1, be1);
    passB_kernel<<<8192, 128>>>(w1, b1, w2, b2);
    params2_kernel<<<1, 64>>>(g2, be2);
    passC_kernel<<<dim3(8192, 2), 128>>>(w3, b3);
    params3_kernel<<<1, 128>>>(g3, be3);
    passD_kernel<<<8192, 256>>>(new_pts);
}

// round 15
// speedup vs baseline: 1.1690x; 1.0306x over previous
#include <cuda_runtime.h>

#define BB 16
#define NN 8192
#define SS 1024
#define KK 32
#define NROWS (BB*SS*KK)        // 524288
#define NINV  (1.0f/524288.0f)  // exact power of two
#define R2 0.04f

typedef unsigned long long ull;

// ---------------- f32x2 packed helpers (Blackwell) ----------------
__device__ __forceinline__ ull pack2(float lo, float hi) {
    ull r;
    asm("mov.b64 %0, {%1, %2};" : "=l"(r) : "r"(__float_as_uint(lo)), "r"(__float_as_uint(hi)));
    return r;
}
__device__ __forceinline__ void unpack2(ull v, float& lo, float& hi) {
    unsigned a, b;
    asm("mov.b64 {%0, %1}, %2;" : "=r"(a), "=r"(b) : "l"(v));
    lo = __uint_as_float(a); hi = __uint_as_float(b);
}
__device__ __forceinline__ ull add2(ull a, ull b) {
    ull d; asm("add.rn.f32x2 %0, %1, %2;" : "=l"(d) : "l"(a), "l"(b)); return d;
}
__device__ __forceinline__ ull mul2(ull a, ull b) {
    ull d; asm("mul.rn.f32x2 %0, %1, %2;" : "=l"(d) : "l"(a), "l"(b)); return d;
}
__device__ __forceinline__ ull fma2(ull a, ull b, ull c) {
    ull d; asm("fma.rn.f32x2 %0, %1, %2, %3;" : "=l"(d) : "l"(a), "l"(b), "l"(c)); return d;
}
__device__ __forceinline__ unsigned redux_max_u32(unsigned v) {
    unsigned r;
    asm("redux.sync.max.u32 %0, %1, 0xffffffff;" : "=r"(r) : "r"(v));
    return r;
}

// ---------------- scratch (device globals: no allocation allowed) ----------------
__device__ int    g_ball[NROWS];
__device__ float4 g_xyzp[BB*NN];
__device__ float4 g_pts4[BB*NN];
__device__ float  g_x[(size_t)NROWS*6];
__device__ float  g_z2[(size_t)NROWS*64];
__device__ float  g_max3[BB*SS*128];
__device__ float  g_min3[BB*SS*128];
__device__ float  g_stats0[27];
__device__ float  g_sum2[64],  g_sumsq2[64];
__device__ float  g_sum3[128], g_sumsq3[128];

// ---------------- FPS: one block per batch, 256 thr x 32 pts, 2 syncs/iter ----------
// Also performs "prep" (g_xyzp / g_pts4 packing) and zeroes the stats accumulators
// (all 16 blocks write the same zeros before any later kernel reads them — benign).
__global__ __launch_bounds__(256) void fps_kernel(const float* __restrict__ xyz,
                                                  const float* __restrict__ pts,
                                                  float* __restrict__ new_xyz) {
    const int b = blockIdx.x;
    const float* base  = xyz + (size_t)b * NN * 3;
    const float* pbase = pts + (size_t)b * NN * 3;
    const int t = threadIdx.x;

    // zero stats (graph replays must re-zero; same-value multi-block writes are benign)
    if (t < 27)  g_stats0[t] = 0.f;
    if (t < 64)  { g_sum2[t] = 0.f; g_sumsq2[t] = 0.f; }
    if (t < 128) { g_sum3[t] = 0.f; g_sumsq3[t] = 0.f; }

    ull px2[16], py2[16], pz2[16];
    float dist[32];
#pragma unroll
    for (int p = 0; p < 16; p++) {
        int i0 = (2*p)*256 + t, i1 = i0 + 256;
        float x0 = base[3*i0], y0 = base[3*i0+1], z0 = base[3*i0+2];
        float x1 = base[3*i1], y1 = base[3*i1+1], z1 = base[3*i1+2];
        px2[p] = pack2(x0, x1); py2[p] = pack2(y0, y1); pz2[p] = pack2(z0, z1);
        g_xyzp[b*NN + i0] = make_float4(x0, y0, z0, fmaf(x0,x0,fmaf(y0,y0,z0*z0)));
        g_xyzp[b*NN + i1] = make_float4(x1, y1, z1, fmaf(x1,x1,fmaf(y1,y1,z1*z1)));
        g_pts4[b*NN + i0] = make_float4(pbase[3*i0], pbase[3*i0+1], pbase[3*i0+2], 0.f);
        g_pts4[b*NN + i1] = make_float4(pbase[3*i1], pbase[3*i1+1], pbase[3*i1+2], 0.f);
        dist[2*p] = 1e10f; dist[2*p+1] = 1e10f;
    }

    __shared__ unsigned s_M[2];
    __shared__ int      s_idx[2];
    if (t == 0) { s_M[0]=0u; s_M[1]=0u; s_idx[0]=0x7fffffff; s_idx[1]=0x7fffffff; }
    float cx = base[0], cy = base[1], cz = base[2];
    __syncthreads();

    float* out = new_xyz + (size_t)b * SS * 3;
    const int lane = t & 31;
    for (int it = 0; it < SS; it++) {
        if (t == 0) { out[3*it] = cx; out[3*it+1] = cy; out[3*it+2] = cz; }
        const int cur = it & 1, nxt = cur ^ 1;
        ull nx2 = pack2(-cx,-cx), ny2 = pack2(-cy,-cy), nz2 = pack2(-cz,-cz);

        // d = (x-cx)^2+(y-cy)^2+(z-cz)^2 (bit-identical to reference form),
        // dist = min(dist,d), track max value only (4-way tree to shorten dep chain)
        float bv0 = 0.f, bv1 = 0.f, bv2 = 0.f, bv3 = 0.f;
#pragma unroll
        for (int p = 0; p < 16; p++) {
            ull dx = add2(px2[p], nx2);
            ull dy = add2(py2[p], ny2);
            ull dz = add2(pz2[p], nz2);
            ull d2 = fma2(dx, dx, fma2(dy, dy, mul2(dz, dz)));
            float d0, d1; unpack2(d2, d0, d1);
            float n0 = fminf(dist[2*p], d0);   dist[2*p]   = n0;
            float n1 = fminf(dist[2*p+1], d1); dist[2*p+1] = n1;
            if (p & 1) { bv1 = fmaxf(bv1, n0); bv3 = fmaxf(bv3, n1); }
            else       { bv0 = fmaxf(bv0, n0); bv2 = fmaxf(bv2, n1); }
        }
        float bv = fmaxf(fmaxf(bv0, bv1), fmaxf(bv2, bv3));
        // all dists >= 0 -> float bits are monotone under u32 compare
        unsigned mb   = __float_as_uint(bv);
        unsigned wmax = redux_max_u32(mb);
        if (lane == 0) atomicMax(&s_M[cur], wmax);
        __syncthreads();

        unsigned M = s_M[cur];
        if (mb == M) {   // only the winning warp(s) pay for the index search
            int cand = 0x7fffffff;
#pragma unroll
            for (int j = 31; j >= 0; j--)
                if (__float_as_uint(dist[j]) == M) cand = j*256 + t;  // lowest j wins
            atomicMin(&s_idx[cur], cand);    // lowest global index wins (first-occurrence)
        }
        if (t == 0) { s_M[nxt] = 0u; s_idx[nxt] = 0x7fffffff; }  // reset other buffer
        __syncthreads();

        int i2 = s_idx[cur];
        cx = base[3*i2]; cy = base[3*i2+1]; cz = base[3*i2+2];   // broadcast LDG
    }
}

// ---------------- ball query: one warp per centroid, pipelined (MLP=4) ----------------
__global__ __launch_bounds__(256) void ball_kernel(const float* __restrict__ new_xyz) {
    int w    = (blockIdx.x * 256 + threadIdx.x) >> 5;  // global centroid id (b*S+s)
    int lane = threadIdx.x & 31;
    int b    = w >> 10;
    const float4* xp = g_xyzp + b * NN;
    float cx = new_xyz[3*w], cy = new_xyz[3*w+1], cz = new_xyz[3*w+2];
    float ss = fmaf(cx,cx, fmaf(cy,cy, cz*cz));
    int* outp = g_ball + w * KK;

    int count = 0, first = 0;
    for (int base = 0; base < NN && count < KK; base += 128) {
        float4 p0 = xp[base      + lane];
        float4 p1 = xp[base + 32 + lane];
        float4 p2 = xp[base + 64 + lane];
        float4 p3 = xp[base + 96 + lane];
#define BQ_STEP(P, OFF) { \
        float dot = fmaf(cx,(P).x, fmaf(cy,(P).y, cz*(P).z)); \
        float sq  = fmaf(-2.f, dot, ss) + (P).w; \
        bool hit  = !(sq > R2); \
        unsigned m = __ballot_sync(0xffffffffu, hit); \
        if (count == 0 && m) first = base + (OFF) + __ffs(m) - 1; \
        int pos = count + __popc(m & ((1u << lane) - 1u)); \
        if (hit && pos < KK) outp[pos] = base + (OFF) + lane; \
        count += __popc(m); }
        BQ_STEP(p0, 0) BQ_STEP(p1, 32) BQ_STEP(p2, 64) BQ_STEP(p3, 96)
#undef BQ_STEP
    }
    if (count < KK && lane >= count && lane < KK) outp[lane] = first;
}

// ---------------- pass A: gather (batched for MLP), store x, accumulate stats ------
__global__ __launch_bounds__(256) void passA_kernel(const float* __restrict__ new_xyz) {
    int gt = blockIdx.x * 256 + threadIdx.x;   // 65536 threads, 8 rows each
    float acc[27];
#pragma unroll
    for (int q = 0; q < 27; q++) acc[q] = 0.f;

    for (int h = 0; h < 2; h++) {
        int idxs[4];
#pragma unroll
        for (int i = 0; i < 4; i++)
            idxs[i] = g_ball[(h*4 + i) * 65536 + gt];   // 4 independent LDGs

        float4 P[4], Q[4];
        float cen[4][3];
#pragma unroll
        for (int i = 0; i < 4; i++) {                    // 20 independent LDGs in flight
            int row = (h*4 + i) * 65536 + gt;
            int b   = row >> 15;
            int bs  = row >> 5;
            P[i] = g_xyzp[b*NN + idxs[i]];
            Q[i] = g_pts4[b*NN + idxs[i]];
            cen[i][0] = new_xyz[3*bs]; cen[i][1] = new_xyz[3*bs+1]; cen[i][2] = new_xyz[3*bs+2];
        }
#pragma unroll
        for (int i = 0; i < 4; i++) {
            int row = (h*4 + i) * 65536 + gt;
            float f[6];
            f[0] = P[i].x - cen[i][0];
            f[1] = P[i].y - cen[i][1];
            f[2] = P[i].z - cen[i][2];
            f[3] = Q[i].x; f[4] = Q[i].y; f[5] = Q[i].z;
            float2* xr = (float2*)(g_x + (size_t)row * 6);
            xr[0] = make_float2(f[0], f[1]);
            xr[1] = make_float2(f[2], f[3]);
            xr[2] = make_float2(f[4], f[5]);
#pragma unroll
            for (int c = 0; c < 6; c++) acc[c] += f[c];
            int pidx = 6;
#pragma unroll
            for (int a = 0; a < 6; a++)
#pragma unroll
                for (int c = a; c < 6; c++) acc[pidx++] = fmaf(f[a], f[c], acc[pidx]);
        }
    }
#pragma unroll
    for (int q = 0; q < 27; q++) {
        float v = acc[q];
#pragma unroll
        for (int o = 16; o > 0; o >>= 1) v += __shfl_down_sync(0xffffffffu, v, o);
        if ((threadIdx.x & 31) == 0) atomicAdd(&g_stats0[q], v);
    }
}

// ---------------- pass B: params1 (folded) + layer1 affine + layer2 GEMM + z2 stats ----
__global__ __launch_bounds__(128) void passB_kernel(const float* __restrict__ w1, const float* __restrict__ b1,
                                                    const float* __restrict__ g1, const float* __restrict__ be1,
                                                    const float* __restrict__ w2, const float* __restrict__ b2) {
    __shared__ __align__(16) float a1T[64][72];   // [k][row]
    __shared__ __align__(16) float w2s[64][64];   // [k][o]
    __shared__ float w1s[64][6], b1s[64], sc1[64], sh1[64], b2s[64];
    __shared__ float mu[6], C2[6][6];
    __shared__ float psum[8][64], psq[8][64];
    int tid = threadIdx.x;

    for (int i = tid; i < 4096; i += 128) { int o = i >> 6, c = i & 63; w2s[c][o] = w2[i]; }
    for (int i = tid; i < 384; i += 128) w1s[i/6][i%6] = w1[i];
    if (tid < 64) { b1s[tid] = b1[tid]; b2s[tid] = b2[tid]; }
    // params1 preamble (replicated per block, bit-identical to old params1_kernel)
    if (tid < 6) mu[tid] = g_stats0[tid] * NINV;
    if (tid >= 64 && tid < 100) {
        int q = tid - 64;
        int i = q / 6, j = q % 6;
        int a = i < j ? i : j, c = i < j ? j : i;
        int pos = 6 + 6*a - (a*(a-1))/2 + (c - a);
        C2[i][j] = g_stats0[pos] * NINV;
    }
    __syncthreads();
    if (tid < 64) {
        float lin = 0.f;
#pragma unroll
        for (int c = 0; c < 6; c++) lin += w1s[tid][c] * mu[c];
        float m = lin + b1s[tid];
        float qv = 0.f;
#pragma unroll
        for (int i = 0; i < 6; i++)
#pragma unroll
            for (int j = 0; j < 6; j++) qv += w1s[tid][i] * w1s[tid][j] * C2[i][j];
        float Ez2 = qv + 2.f * b1s[tid] * lin + b1s[tid]*b1s[tid];
        float var = Ez2 - m*m;
        float sc  = g1[tid] * rsqrtf(var + 1e-5f);
        sc1[tid] = sc;
        sh1[tid] = be1[tid] - m * sc;
    }
    __syncthreads();

    int rowBase = blockIdx.x * 64;
    {   // stage 1: a1T[o][r] = relu(affine1(W1 x + b1)), transposed store
        int r = tid >> 1, o0 = (tid & 1) * 32;
        const float2* xr2 = (const float2*)(g_x + (size_t)(rowBase + r) * 6);
        float2 v0 = xr2[0], v1 = xr2[1], v2 = xr2[2];
        float x0=v0.x, x1=v0.y, x2=v1.x, x3=v1.y, x4=v2.x, x5=v2.y;
#pragma unroll
        for (int c = 0; c < 32; c++) {
            int o = o0 + c;
            float z = b1s[o];
            z = fmaf(w1s[o][0],x0, z); z = fmaf(w1s[o][1],x1, z); z = fmaf(w1s[o][2],x2, z);
            z = fmaf(w1s[o][3],x3, z); z = fmaf(w1s[o][4],x4, z); z = fmaf(w1s[o][5],x5, z);
            a1T[o][r] = fmaxf(fmaf(z, sc1[o], sh1[o]), 0.f);
        }
    }
    __syncthreads();

    int tx = tid & 15, ty = tid >> 4;       // tx: 4-col group, ty: 8-row group
    ull acc[4][4];                          // [row-pair][col]
#pragma unroll
    for (int j = 0; j < 4; j++) {
        ull bp = pack2(b2s[tx*4+j], b2s[tx*4+j]);
#pragma unroll
        for (int pi = 0; pi < 4; pi++) acc[pi][j] = bp;
    }

#pragma unroll 8
    for (int k = 0; k < 64; k++) {
        ulonglong2 ap0 = *(const ulonglong2*)&a1T[k][ty*8];
        ulonglong2 ap1 = *(const ulonglong2*)&a1T[k][ty*8 + 4];
        float4 wv = *(const float4*)&w2s[k][tx*4];
        ull wd0 = pack2(wv.x, wv.x), wd1 = pack2(wv.y, wv.y);
        ull wd2 = pack2(wv.z, wv.z), wd3 = pack2(wv.w, wv.w);
        ull ar[4] = {ap0.x, ap0.y, ap1.x, ap1.y};
#pragma unroll
        for (int pi = 0; pi < 4; pi++) {
            acc[pi][0] = fma2(ar[pi], wd0, acc[pi][0]);
            acc[pi][1] = fma2(ar[pi], wd1, acc[pi][1]);
            acc[pi][2] = fma2(ar[pi], wd2, acc[pi][2]);
            acc[pi][3] = fma2(ar[pi], wd3, acc[pi][3]);
        }
    }

    float z[8][4];
#pragma unroll
    for (int pi = 0; pi < 4; pi++)
#pragma unroll
        for (int j = 0; j < 4; j++) unpack2(acc[pi][j], z[2*pi][j], z[2*pi+1][j]);

    float cs[4] = {0,0,0,0}, cq[4] = {0,0,0,0};
#pragma unroll
    for (int rr = 0; rr < 8; rr++) {
        float4 v = make_float4(z[rr][0], z[rr][1], z[rr][2], z[rr][3]);
        *(float4*)&g_z2[(size_t)(rowBase + ty*8 + rr) * 64 + tx*4] = v;
        cs[0]+=v.x; cs[1]+=v.y; cs[2]+=v.z; cs[3]+=v.w;
        cq[0]=fmaf(v.x,v.x,cq[0]); cq[1]=fmaf(v.y,v.y,cq[1]);
        cq[2]=fmaf(v.z,v.z,cq[2]); cq[3]=fmaf(v.w,v.w,cq[3]);
    }
#pragma unroll
    for (int j = 0; j < 4; j++) { psum[ty][tx*4+j] = cs[j]; psq[ty][tx*4+j] = cq[j]; }
    __syncthreads();
    if (tid < 64) {
        float s = 0.f, s2 = 0.f;
#pragma unroll
        for (int y = 0; y < 8; y++) { s += psum[y][tid]; s2 += psq[y][tid]; }
        atomicAdd(&g_sum2[tid], s);
        atomicAdd(&g_sumsq2[tid], s2);
    }
}

// ---------------- pass C: params2 (folded) + layer3 GEMM + stats + group max/min ----
__global__ __launch_bounds__(128) void passC_kernel(const float* __restrict__ w3, const float* __restrict__ b3,
                                                    const float* __restrict__ g2, const float* __restrict__ be2) {
    __shared__ __align__(16) float a2T[64][72];   // [k][row]
    __shared__ __align__(16) float w3s[64][64];   // [k][o-in-half]
    __shared__ float sc2[64], sh2[64], b3s[64];
    __shared__ float psum[8][64], psq[8][64], pmax[8][64], pmin[8][64];
    int tid = threadIdx.x;
    int colBase = blockIdx.y * 64;

    for (int i = tid; i < 4096; i += 128) {
        int o = i >> 6, c = i & 63;
        w3s[c][o] = w3[(size_t)colBase * 64 + i];   // = w3[(colBase+o)*64 + c], contiguous read
    }
    if (tid < 64) {
        // params2 preamble (replicated per block, bit-identical to old params2_kernel)
        float m = g_sum2[tid] * NINV;
        float var = g_sumsq2[tid] * NINV - m*m;
        float sc = g2[tid] * rsqrtf(var + 1e-5f);
        sc2[tid] = sc; sh2[tid] = be2[tid] - m * sc;
        b3s[tid] = b3[colBase + tid];
    }
    __syncthreads();

    int rowBase = blockIdx.x * 64;
    {   // stage 1: a2T[o][r] = relu(affine2(z2)), transposed store
        int r = tid >> 1, o0 = (tid & 1) * 32;
        const float* zr = g_z2 + (size_t)(rowBase + r) * 64 + o0;
#pragma unroll
        for (int q = 0; q < 8; q++) {
            float4 v = *(const float4*)&zr[q*4];
            int o = o0 + q*4;
            a2T[o  ][r] = fmaxf(fmaf(v.x, sc2[o  ], sh2[o  ]), 0.f);
            a2T[o+1][r] = fmaxf(fmaf(v.y, sc2[o+1], sh2[o+1]), 0.f);
            a2T[o+2][r] = fmaxf(fmaf(v.z, sc2[o+2], sh2[o+2]), 0.f);
            a2T[o+3][r] = fmaxf(fmaf(v.w, sc2[o+3], sh2[o+3]), 0.f);
        }
    }
    __syncthreads();

    int tx = tid & 15, ty = tid >> 4;
    ull acc[4][4];
#pragma unroll
    for (int j = 0; j < 4; j++) {
        ull bp = pack2(b3s[tx*4+j], b3s[tx*4+j]);
#pragma unroll
        for (int pi = 0; pi < 4; pi++) acc[pi][j] = bp;
    }

#pragma unroll 8
    for (int k = 0; k < 64; k++) {
        ulonglong2 ap0 = *(const ulonglong2*)&a2T[k][ty*8];
        ulonglong2 ap1 = *(const ulonglong2*)&a2T[k][ty*8 + 4];
        float4 wv = *(const float4*)&w3s[k][tx*4];
        ull wd0 = pack2(wv.x, wv.x), wd1 = pack2(wv.y, wv.y);
        ull wd2 = pack2(wv.z, wv.z), wd3 = pack2(wv.w, wv.w);
        ull ar[4] = {ap0.x, ap0.y, ap1.x, ap1.y};
#pragma unroll
        for (int pi = 0; pi < 4; pi++) {
            acc[pi][0] = fma2(ar[pi], wd0, acc[pi][0]);
            acc[pi][1] = fma2(ar[pi], wd1, acc[pi][1]);
            acc[pi][2] = fma2(ar[pi], wd2, acc[pi][2]);
            acc[pi][3] = fma2(ar[pi], wd3, acc[pi][3]);
        }
    }

    float z[8][4];
#pragma unroll
    for (int pi = 0; pi < 4; pi++)
#pragma unroll
        for (int j = 0; j < 4; j++) unpack2(acc[pi][j], z[2*pi][j], z[2*pi+1][j]);

    float cs[4] = {0,0,0,0}, cq[4] = {0,0,0,0};
    float mx[4] = {-1e30f,-1e30f,-1e30f,-1e30f}, mn[4] = {1e30f,1e30f,1e30f,1e30f};
#pragma unroll
    for (int rr = 0; rr < 8; rr++) {
#pragma unroll
        for (int j = 0; j < 4; j++) {
            float v = z[rr][j];
            cs[j] += v; cq[j] = fmaf(v, v, cq[j]);
            mx[j] = fmaxf(mx[j], v); mn[j] = fminf(mn[j], v);
        }
    }
#pragma unroll
    for (int j = 0; j < 4; j++) {
        psum[ty][tx*4+j] = cs[j]; psq[ty][tx*4+j] = cq[j];
        pmax[ty][tx*4+j] = mx[j]; pmin[ty][tx*4+j] = mn[j];
    }
    __syncthreads();
    if (tid < 64) {
        float s = 0.f, s2 = 0.f;
#pragma unroll
        for (int y = 0; y < 8; y++) { s += psum[y][tid]; s2 += psq[y][tid]; }
        atomicAdd(&g_sum3[colBase + tid], s);
        atomicAdd(&g_sumsq3[colBase + tid], s2);
    }
    {   // per-32-row-group max/min: group 0 = ty 0..3, group 1 = ty 4..7
        int g = tid >> 6, c = tid & 63;
        float M = -1e30f, m = 1e30f;
#pragma unroll
        for (int y = 0; y < 4; y++) {
            M = fmaxf(M, pmax[g*4 + y][c]);
            m = fminf(m, pmin[g*4 + y][c]);
        }
        int gid = blockIdx.x * 2 + g;
        g_max3[(size_t)gid * 128 + colBase + c] = M;
        g_min3[(size_t)gid * 128 + colBase + c] = m;
    }
}

// ---------------- pass D: params3 (folded) + affine3 on pre-reduced max/min + relu ----
__global__ __launch_bounds__(256) void passD_kernel(const float* __restrict__ g3, const float* __restrict__ be3,
                                                    float* __restrict__ out_pts) {
    __shared__ float sc3s[128], sh3s[128];
    int t = threadIdx.x;
    if (t < 128) {
        // params3 preamble (replicated per block, bit-identical to old params3_kernel)
        float m = g_sum3[t] * NINV;
        float var = g_sumsq3[t] * NINV - m*m;
        float sc = g3[t] * rsqrtf(var + 1e-5f);
        sc3s[t] = sc; sh3s[t] = be3[t] - m * sc;
    }
    __syncthreads();
    int idx = blockIdx.x * 256 + t;   // gid*128 + c, 2M total
    int c = idx & 127;
    float sc = sc3s[c], sh = sh3s[c];
    float v = (sc >= 0.f) ? g_max3[idx] : g_min3[idx];
    out_pts[idx] = fmaxf(fmaf(v, sc, sh), 0.f);
}

// ---------------- launch ----------------
extern "C" void kernel_launch(void* const* d_in, const int* in_sizes, int n_in,
                              void* d_out, int out_size) {
    const float* xyz = (const float*)d_in[0];
    const float* pts = (const float*)d_in[1];
    const float* w1  = (const float*)d_in[2];
    const float* b1  = (const float*)d_in[3];
    const float* g1  = (const float*)d_in[4];
    const float* be1 = (const float*)d_in[5];
    const float* w2  = (const float*)d_in[6];
    const float* b2  = (const float*)d_in[7];
    const float* g2  = (const float*)d_in[8];
    const float* be2 = (const float*)d_in[9];
    const float* w3  = (const float*)d_in[10];
    const float* b3  = (const float*)d_in[11];
    const float* g3  = (const float*)d_in[12];
    const float* be3 = (const float*)d_in[13];

    float* out      = (float*)d_out;
    float* new_xyz  = out;                 // 16*1024*3 = 49152 floats
    float* new_pts  = out + 49152;         // 16*1024*128 floats

    fps_kernel<<<BB, 256>>>(xyz, pts, new_xyz);                  // #1
    ball_kernel<<<2048, 256>>>(new_xyz);                         // #2
    passA_kernel<<<256, 256>>>(new_xyz);                         // #3
    passB_kernel<<<8192, 128>>>(w1, b1, g1, be1, w2, b2);        // #4 -> profiled
    passC_kernel<<<dim3(8192, 2), 128>>>(w3, b3, g2, be2);       // #5
    passD_kernel<<<8192, 256>>>(g3, be3, new_pts);               // #6
}